// round 1
// baseline (speedup 1.0000x reference)
#include <cuda_runtime.h>
#include <math.h>

#define KLEN  4096
#define NFREQ 2049      // K/2 + 1
#define NSIG  12
#define NBATCH 64
#define NLAG  51        // 2*25 + 1
#define NTAU  26        // tau = 0..25
#define NPAIR 78        // 12*13/2 unique (n<=m) pairs
#define SLICES 8
#define CHUNK 257       // ceil(2049/8)

// -------- device scratch (static: no allocations allowed) --------
__device__ float2 g_dft64[64 * 64];                 // (cos, sin) of 2*pi*j*a/64 at [j*64+a]
__device__ float2 g_lag[NFREQ * NTAU];              // (w*cos/K, w*sin/K) at [f*26+tau]
__device__ float2 g_spec[NBATCH * NSIG * NFREQ];    // PHAT-normalized spectra

// ================= init: twiddle tables =================
__global__ void init_tables_kernel() {
    int t = blockIdx.x * blockDim.x + threadIdx.x;
    int stride = gridDim.x * blockDim.x;
    for (int i = t; i < 64 * 64; i += stride) {
        int j = i >> 6, a = i & 63;
        float s, c;
        sincospif((float)(j * a) * (1.0f / 32.0f), &s, &c);   // 2*pi*j*a/64 = pi*(j*a/32)
        g_dft64[i] = make_float2(c, s);
    }
    for (int i = t; i < NFREQ * NTAU; i += stride) {
        int f = i / NTAU, tau = i % NTAU;
        float s, c;
        sincospif((float)(f * tau) * (1.0f / 2048.0f), &s, &c); // 2*pi*f*tau/4096
        float w = ((f == 0) || (f == 2048)) ? 1.0f : 2.0f;
        w *= (1.0f / (float)KLEN);
        g_lag[i] = make_float2(w * c, w * s);
    }
}

// ================= FFT (64x64 four-step) + PHAT =================
// One CTA per signal (768 CTAs), 256 threads.
// x[k] with k = 64*a + b.  Y[d][b] = sum_a x[64a+b] * W64^{ad}
// Z[d][b] = Y[d][b] * W4096^{bd};  X[64c+d] = sum_b Z[d][b] * W64^{bc}
__global__ __launch_bounds__(256) void fft_phat_kernel(const float* __restrict__ x) {
    extern __shared__ float smem[];
    float*  xs  = smem;                              // 4096 floats
    float2* Yt  = (float2*)(smem + KLEN);            // [b][d] padded: b*66 + d
    float2* dft = Yt + 64 * 66;                      // 4096 float2

    const int t = threadIdx.x;
    const int sig = blockIdx.x;
    const float* xin = x + (size_t)sig * KLEN;

    for (int i = t; i < KLEN; i += 256) xs[i] = xin[i];
    for (int i = t; i < 64 * 64; i += 256) dft[i] = g_dft64[i];
    __syncthreads();

    // ---- stage 1 + twiddle ----
    {
        int b = t & 63, d0 = t >> 6;
        #pragma unroll
        for (int i = 0; i < 16; i++) {
            int d = d0 + 4 * i;
            float yr = 0.f, yi = 0.f;
            const float2* row = dft + d * 64;
            #pragma unroll 8
            for (int a = 0; a < 64; a++) {
                float xv = xs[a * 64 + b];
                float2 cs = row[a];
                yr += xv * cs.x;     // * (cos - i sin)
                yi -= xv * cs.y;
            }
            float s, c;
            sincospif((float)(b * d) * (1.0f / 2048.0f), &s, &c); // W4096^{bd} = c - i s
            float zr = yr * c + yi * s;
            float zi = yi * c - yr * s;
            Yt[b * 66 + d] = make_float2(zr, zi);
        }
    }
    __syncthreads();

    // ---- stage 2: need f = 64c + d for f <= 2048  (c in [0,32]) ----
    {
        int d = t & 63, c0 = t >> 6;
        float2* outp = g_spec + (size_t)sig * NFREQ;
        #pragma unroll
        for (int j = 0; j < 9; j++) {
            int cc = c0 + 4 * j;
            if (cc <= 32) {
                float Xr = 0.f, Xi = 0.f;
                const float2* row = dft + cc * 64;
                #pragma unroll 8
                for (int bb = 0; bb < 64; bb++) {
                    float2 z = Yt[bb * 66 + d];
                    float2 cs = row[bb];
                    Xr += z.x * cs.x + z.y * cs.y;   // z * (cos - i sin)
                    Xi += z.y * cs.x - z.x * cs.y;
                }
                int f = cc * 64 + d;
                if (f <= 2048) {
                    float mag = sqrtf(Xr * Xr + Xi * Xi);
                    float inv = 1.0f / (mag + 1e-12f);
                    outp[f] = make_float2(Xr * inv, Xi * inv);
                }
            }
        }
    }
}

// ================= GCC: pairwise cross-spectrum x lag twiddles =================
// grid = (64 batches, 8 f-slices), 1024 threads.
// Thread owns (pair p in [0,78), tau-pair {2g, 2g+1}); accumulates 4 lags over
// its 257-frequency slice; atomicAdds into out (exploiting g_nm[t] = g_mn[-t]).
__global__ __launch_bounds__(1024) void gcc_kernel(float* __restrict__ out) {
    extern __shared__ float2 sm2[];
    float2* su  = sm2;                       // 12 * CHUNK spectra
    float2* stw = sm2 + NSIG * CHUNK;        // CHUNK * 26 lag twiddles

    const int t = threadIdx.x;
    const int bidx = blockIdx.x;
    const int f0 = blockIdx.y * CHUNK;

    for (int i = t; i < NSIG * CHUNK; i += 1024) {
        int sig = i / CHUNK, fl = i - sig * CHUNK;
        int f = f0 + fl;
        su[i] = (f < NFREQ) ? g_spec[((size_t)bidx * NSIG + sig) * NFREQ + f]
                            : make_float2(0.f, 0.f);
    }
    for (int i = t; i < CHUNK * NTAU; i += 1024) {
        int fl = i / NTAU;
        int f = f0 + fl;
        stw[i] = (f < NFREQ) ? g_lag[(size_t)f * NTAU + (i - fl * NTAU)]
                             : make_float2(0.f, 0.f);
    }
    __syncthreads();

    if (t >= NPAIR * 13) return;
    const int p  = t / 13;
    const int tg = t - p * 13;
    const int tau0 = 2 * tg, tau1 = tau0 + 1;

    // decode triangular pair index p -> (n, m) with n <= m
    int n = 0, rem = p;
    #pragma unroll
    for (int k = 0; k < NSIG; k++) {
        int cnt = NSIG - k;
        if (rem < cnt) { n = k; break; }
        rem -= cnt;
    }
    const int m = n + rem;

    const float2* un = su + n * CHUNK;
    const float2* um = su + m * CHUNK;

    float gp0 = 0.f, gm0 = 0.f, gp1 = 0.f, gm1 = 0.f;
    #pragma unroll 4
    for (int fl = 0; fl < CHUNK; fl++) {
        float2 a = un[fl];
        float2 b = um[fl];
        float U = a.x * b.x + a.y * b.y;   // Re(u_n * conj(u_m))
        float V = a.y * b.x - a.x * b.y;   // Im(u_n * conj(u_m))
        float2 w0 = stw[fl * NTAU + tau0];
        float2 w1 = stw[fl * NTAU + tau1];
        float uc0 = U * w0.x, vs0 = V * w0.y;
        float uc1 = U * w1.x, vs1 = V * w1.y;
        gp0 += uc0 - vs0;   // g[+tau0]
        gm0 += uc0 + vs0;   // g[-tau0]
        gp1 += uc1 - vs1;
        gm1 += uc1 + vs1;
    }

    float* ob  = out + (size_t)bidx * NSIG * NSIG * NLAG;
    float* onm = ob + (n * NSIG + m) * NLAG;
    atomicAdd(&onm[tau0], gp0);
    atomicAdd(&onm[tau1], gp1);
    if (tau0 > 0) atomicAdd(&onm[NLAG - tau0], gm0);
    atomicAdd(&onm[NLAG - tau1], gm1);
    if (n != m) {
        float* omn = ob + (m * NSIG + n) * NLAG;
        atomicAdd(&omn[tau0], gm0);                     // g_mn[+tau] = g_nm[-tau]
        atomicAdd(&omn[tau1], gm1);
        if (tau0 > 0) atomicAdd(&omn[NLAG - tau0], gp0);
        atomicAdd(&omn[NLAG - tau1], gp1);
    }
}

// ================= launch =================
extern "C" void kernel_launch(void* const* d_in, const int* in_sizes, int n_in,
                              void* d_out, int out_size) {
    const float* x = (const float*)d_in[0];
    float* out = (float*)d_out;

    const int fft_smem = KLEN * (int)sizeof(float)
                       + 64 * 66 * (int)sizeof(float2)
                       + 64 * 64 * (int)sizeof(float2);          // 82,944 B
    const int gcc_smem = (NSIG * CHUNK + CHUNK * NTAU) * (int)sizeof(float2); // 78,128 B

    cudaFuncSetAttribute(fft_phat_kernel, cudaFuncAttributeMaxDynamicSharedMemorySize, fft_smem);
    cudaFuncSetAttribute(gcc_kernel,      cudaFuncAttributeMaxDynamicSharedMemorySize, gcc_smem);

    init_tables_kernel<<<64, 256>>>();
    fft_phat_kernel<<<NBATCH * NSIG, 256, fft_smem>>>(x);
    cudaMemsetAsync(d_out, 0, (size_t)out_size * sizeof(float));
    gcc_kernel<<<dim3(NBATCH, SLICES), 1024, gcc_smem>>>(out);
}

// round 2
// speedup vs baseline: 1.6658x; 1.6658x over previous
#include <cuda_runtime.h>
#include <math.h>

#define KLEN   4096
#define NFREQ  2049      // K/2 + 1
#define NH     1025      // folded frequencies h = 0..1024  (f=h paired with f=2048-h)
#define NSIG   12
#define NBATCH 64
#define NLAG   51        // 2*25 + 1
#define NTAU   26        // tau = 0..25
#define NPAIR  78        // 12*13/2 unique (n<=m) pairs
#define NS     8         // frequency slices for gcc kernel
#define CH     129       // folded freqs per CTA (8*129 = 1032 >= 1025, padded)
#define GCC_BLOCK 320    // 4 groups x 80 (78 active pairs per group)
#define NGRP   4
#define GRP    80
#define OUTB   (NSIG*NSIG*NLAG)   // 7344 floats per batch

// -------- device scratch (static: no allocations allowed) --------
__device__ float2 g_dft64[64 * 64];               // (cos,sin) of 2*pi*j*a/64 at [j*64+a]
__device__ float4 g_lag4[NH * NTAU];              // (w*c, w*c, w*s, w*s) at [h*26+tau]
__device__ float2 g_spec[NBATCH * NSIG * NFREQ];  // PHAT-normalized spectra
__device__ float  g_part[NS][NBATCH][OUTB];       // per-slice partial outputs (~15 MB)

// -------- packed fp32x2 helpers --------
__device__ __forceinline__ unsigned long long fma_x2(unsigned long long a,
                                                     unsigned long long b,
                                                     unsigned long long c) {
    unsigned long long d;
    asm("fma.rn.f32x2 %0, %1, %2, %3;" : "=l"(d) : "l"(a), "l"(b), "l"(c));
    return d;
}
__device__ __forceinline__ unsigned long long pack2(float lo, float hi) {
    unsigned long long d;
    asm("mov.b64 %0, {%1, %2};" : "=l"(d) : "f"(lo), "f"(hi));
    return d;
}
__device__ __forceinline__ void unpack2(unsigned long long v, float& lo, float& hi) {
    asm("mov.b64 {%0, %1}, %2;" : "=f"(lo), "=f"(hi) : "l"(v));
}

// ================= init: twiddle tables =================
__global__ void init_tables_kernel() {
    int t = blockIdx.x * blockDim.x + threadIdx.x;
    int stride = gridDim.x * blockDim.x;
    for (int i = t; i < 64 * 64; i += stride) {
        int j = i >> 6, a = i & 63;
        float s, c;
        sincospif((float)(j * a) * (1.0f / 32.0f), &s, &c);   // 2*pi*j*a/64
        g_dft64[i] = make_float2(c, s);
    }
    for (int i = t; i < NH * NTAU; i += stride) {
        int h = i / NTAU, tau = i - h * NTAU;
        float s, c;
        sincospif((float)(h * tau) * (1.0f / 2048.0f), &s, &c); // 2*pi*h*tau/4096
        float w = ((h == 0) ? 1.0f : 2.0f) * (1.0f / (float)KLEN);
        g_lag4[i] = make_float4(w * c, w * c, w * s, w * s);
    }
}

// ================= FFT (64x64 four-step, Hermitian stage 1) + PHAT =================
// x[k], k = 64*a + b.  Y[d][b] = sum_a x[64a+b] W64^{ad}  (real input: Y[64-d]=conj(Y[d]))
// Z[d][b] = Y[d][b] * W4096^{bd};  X[64c+d] = sum_b Z[d][b] * W64^{bc}
__global__ __launch_bounds__(256) void fft_phat_kernel(const float* __restrict__ x) {
    extern __shared__ float smem[];
    float*  xs  = smem;                              // 4096 floats
    float2* Yt  = (float2*)(smem + KLEN);            // [b][d]: b*66 + d (padded)
    float2* dft = Yt + 64 * 66;                      // 4096 float2

    const int t = threadIdx.x;
    const int sig = blockIdx.x;
    const float* xin = x + (size_t)sig * KLEN;

    for (int i = t; i < KLEN; i += 256) xs[i] = xin[i];
    for (int i = t; i < 64 * 64; i += 256) dft[i] = g_dft64[i];
    __syncthreads();

    // ---- stage 1 (d <= 32 only; mirror d in [1,31]) + twiddle ----
    {
        int b = t & 63, d0 = t >> 6;
        float2 e = dft[64 + b];   // (cos, sin)(2*pi*b/64)
        #pragma unroll
        for (int i = 0; i < 9; i++) {
            int d = d0 + 4 * i;
            if (d > 32) continue;
            float yr = 0.f, yi = 0.f;
            const float2* row = dft + d * 64;
            #pragma unroll 8
            for (int a = 0; a < 64; a++) {
                float xv = xs[a * 64 + b];
                float2 cs = row[a];
                yr += xv * cs.x;    // * (cos - i sin)
                yi -= xv * cs.y;
            }
            float s, c;
            sincospif((float)(b * d) * (1.0f / 2048.0f), &s, &c); // W4096^{bd} = c - i s
            Yt[b * 66 + d] = make_float2(yr * c + yi * s, yi * c - yr * s);
            if (d >= 1 && d <= 31) {
                // Z[64-d] = conj(Y[d]) * (cos th' - i sin th'), th' = 2pi b/64 - th
                float tmr = e.x * c + e.y * s;     // cos th'
                float tms = e.y * c - e.x * s;     // sin th'
                Yt[b * 66 + (64 - d)] =
                    make_float2(yr * tmr - yi * tms, -(yr * tms + yi * tmr));
            }
        }
    }
    __syncthreads();

    // ---- stage 2: f = 64c + d for f <= 2048 (c in [0,32]) ----
    {
        int d = t & 63, c0 = t >> 6;
        float2* outp = g_spec + (size_t)sig * NFREQ;
        #pragma unroll
        for (int j = 0; j < 9; j++) {
            int cc = c0 + 4 * j;
            if (cc <= 32) {
                float Xr = 0.f, Xi = 0.f;
                const float2* row = dft + cc * 64;
                #pragma unroll 8
                for (int bb = 0; bb < 64; bb++) {
                    float2 z = Yt[bb * 66 + d];
                    float2 cs = row[bb];
                    Xr += z.x * cs.x + z.y * cs.y;
                    Xi += z.y * cs.x - z.x * cs.y;
                }
                int f = cc * 64 + d;
                if (f <= 2048) {
                    float mag = sqrtf(Xr * Xr + Xi * Xi);
                    float inv = 1.0f / (mag + 1e-12f);
                    outp[f] = make_float2(Xr * inv, Xi * inv);
                }
            }
        }
    }
}

// ================= GCC: folded cross-spectrum x lag twiddles (f32x2 packed) =================
// grid (64 batches, 8 slices), block 320 = 4 groups x 80 (78 pairs active).
// Thread = one pair, all 26 taus; folded freqs f and 2048-f processed together:
//   even tau: g+ = wc*(U1+U2) - ws*(V1-V2);  g- = wc*(U1+U2) + ws*(V1-V2)
//   odd  tau: g+ = wc*(U1-U2) - ws*(V1+V2);  g- = wc*(U1-U2) + ws*(V1+V2)
__global__ __launch_bounds__(GCC_BLOCK) void gcc_kernel() {
    extern __shared__ float smem[];
    float2* suA  = (float2*)smem;                   // [12][CH] spectra at f
    float2* suB  = suA + NSIG * CH;                 // [12][CH] spectra at 2048-f
    float4* T    = (float4*)(suB + NSIG * CH);      // [CH][26] packed twiddles
    float*  sacc = (float*)(T + CH * NTAU);         // [78][52] cross-group accum

    const int t = threadIdx.x;
    const int bidx = blockIdx.x;
    const int f0 = blockIdx.y * CH;

    for (int i = t; i < NSIG * CH; i += GCC_BLOCK) {
        int sig = i / CH, hl = i - sig * CH;
        int f = f0 + hl;
        const float2* sp = g_spec + ((size_t)bidx * NSIG + sig) * NFREQ;
        suA[i] = (f <= 1024) ? sp[f] : make_float2(0.f, 0.f);
        suB[i] = (f <= 1023) ? sp[2048 - f] : make_float2(0.f, 0.f); // f=1024 self-pairs: zero
    }
    for (int i = t; i < CH * NTAU; i += GCC_BLOCK) {
        int hl = i / NTAU;
        int f = f0 + hl;
        T[i] = (f <= 1024) ? g_lag4[f * NTAU + (i - hl * NTAU)]
                           : make_float4(0.f, 0.f, 0.f, 0.f);
    }
    for (int i = t; i < NPAIR * 52; i += GCC_BLOCK) sacc[i] = 0.f;
    __syncthreads();

    const int g = t / GRP, u = t - g * GRP;
    if (u < NPAIR) {
        // decode triangular pair u -> (n, m), n <= m
        int n = 0, rem = u;
        #pragma unroll
        for (int k = 0; k < NSIG; k++) {
            int cnt = NSIG - k;
            if (rem < cnt) { n = k; break; }
            rem -= cnt;
        }
        const int m = n + rem;

        const float2* pAn = suA + n * CH;
        const float2* pAm = suA + m * CH;
        const float2* pBn = suB + n * CH;
        const float2* pBm = suB + m * CH;

        unsigned long long acc[NTAU];   // packed (g+, g-)
        #pragma unroll
        for (int i = 0; i < NTAU; i++) acc[i] = 0ull;

        const int h0 = g * 33;
        const int h1 = (h0 + 33 < CH) ? h0 + 33 : CH;
        for (int hl = h0; hl < h1; hl++) {
            float2 a1 = pAn[hl], b1 = pAm[hl];
            float2 a2 = pBn[hl], b2 = pBm[hl];
            float U1 = a1.x * b1.x + a1.y * b1.y;
            float V1 = a1.y * b1.x - a1.x * b1.y;
            float U2 = a2.x * b2.x + a2.y * b2.y;
            float V2 = a2.y * b2.x - a2.x * b2.y;
            float Ue = U1 + U2, Uo = U1 - U2;
            float Vme = V1 - V2, Vpo = V1 + V2;
            unsigned long long pUe = pack2(Ue, Ue);
            unsigned long long pUo = pack2(Uo, Uo);
            unsigned long long pVe = pack2(-Vme, Vme);
            unsigned long long pVo = pack2(-Vpo, Vpo);
            const longlong2* tw = (const longlong2*)(T + (size_t)hl * NTAU);
            #pragma unroll
            for (int tau = 0; tau < NTAU; tau++) {
                longlong2 w = tw[tau];   // .x = (wc,wc), .y = (ws,ws)
                acc[tau] = fma_x2((unsigned long long)w.x, (tau & 1) ? pUo : pUe, acc[tau]);
                acc[tau] = fma_x2((unsigned long long)w.y, (tau & 1) ? pVo : pVe, acc[tau]);
            }
        }
        #pragma unroll
        for (int tau = 0; tau < NTAU; tau++) {
            float gp, gm;
            unpack2(acc[tau], gp, gm);
            atomicAdd(&sacc[u * 52 + tau], gp);
            atomicAdd(&sacc[u * 52 + 26 + tau], gm);
        }
    }
    __syncthreads();

    // cooperative coalesced write of the full [12][12][51] block for this (batch, slice)
    float* outp = g_part[blockIdx.y][bidx];
    for (int idx = t; idx < OUTB; idx += GCC_BLOCK) {
        int n = idx / (NSIG * NLAG);
        int r = idx - n * (NSIG * NLAG);
        int mm = r / NLAG, l = r - mm * NLAG;
        int lo = (n < mm) ? n : mm;
        int hi = (n < mm) ? mm : n;
        int p = lo * NSIG - (lo * (lo - 1)) / 2 + (hi - lo);
        bool fwd = (n <= mm);
        float v;
        if (l <= 25) v = sacc[p * 52 + (fwd ? l : 26 + l)];
        else { int tau = NLAG - l; v = sacc[p * 52 + (fwd ? 26 + tau : tau)]; }
        outp[idx] = v;
    }
}

// ================= reduce partials =================
__global__ void reduce_kernel(float* __restrict__ out) {
    int i = blockIdx.x * blockDim.x + threadIdx.x;
    const int total = NBATCH * OUTB / 4;
    if (i < total) {
        float4 s = make_float4(0.f, 0.f, 0.f, 0.f);
        #pragma unroll
        for (int sl = 0; sl < NS; sl++) {
            float4 v = ((const float4*)(&g_part[sl][0][0]))[i];
            s.x += v.x; s.y += v.y; s.z += v.z; s.w += v.w;
        }
        ((float4*)out)[i] = s;
    }
}

// ================= launch =================
extern "C" void kernel_launch(void* const* d_in, const int* in_sizes, int n_in,
                              void* d_out, int out_size) {
    const float* x = (const float*)d_in[0];
    float* out = (float*)d_out;

    const int fft_smem = KLEN * (int)sizeof(float)
                       + 64 * 66 * (int)sizeof(float2)
                       + 64 * 64 * (int)sizeof(float2);           // 82,944 B
    const int gcc_smem = (2 * NSIG * CH) * (int)sizeof(float2)
                       + CH * NTAU * (int)sizeof(float4)
                       + NPAIR * 52 * (int)sizeof(float);         // 94,656 B

    cudaFuncSetAttribute(fft_phat_kernel, cudaFuncAttributeMaxDynamicSharedMemorySize, fft_smem);
    cudaFuncSetAttribute(gcc_kernel,      cudaFuncAttributeMaxDynamicSharedMemorySize, gcc_smem);

    init_tables_kernel<<<64, 256>>>();
    fft_phat_kernel<<<NBATCH * NSIG, 256, fft_smem>>>(x);
    gcc_kernel<<<dim3(NBATCH, NS), GCC_BLOCK, gcc_smem>>>();
    const int total4 = NBATCH * OUTB / 4;
    reduce_kernel<<<(total4 + 255) / 256, 256>>>(out);
}

// round 3
// speedup vs baseline: 2.0413x; 1.2254x over previous
#include <cuda_runtime.h>
#include <math.h>

#define KLEN   4096
#define NFREQ  2049      // K/2 + 1
#define NH     1025      // folded frequencies h = 0..1024  (f=h paired with f=2048-h)
#define NSIG   12
#define NBATCH 64
#define NLAG   51        // 2*25 + 1
#define NTAU   26        // tau = 0..25
#define NPAIR  78        // 12*13/2 unique (n<=m) pairs
#define NS     8         // frequency slices
#define CH     129       // folded freqs per slice (8*129 = 1032 >= 1025)
#define BPG    4         // batches per gcc CTA
#define GCC_BLOCK 320    // 4 batch-groups x 80 threads (78 active pairs each)
#define OUTB   (NSIG*NSIG*NLAG)   // 7344 floats per batch

// -------- device scratch (static: no allocations allowed) --------
__device__ float2 g_dft64[64 * 64];               // (cos,sin) of 2*pi*j*a/64 at [j*64+a]
__device__ float4 g_lag4[NH * NTAU];              // (w*c, w*c, w*s, w*s) at [h*26+tau]
__device__ float2 g_spec[NBATCH * NSIG * NFREQ];  // PHAT-normalized spectra
__device__ unsigned long long g_part2[NS][NBATCH][NPAIR][NTAU];  // packed (g+, g-) partials

// -------- packed fp32x2 helpers --------
__device__ __forceinline__ unsigned long long fma_x2(unsigned long long a,
                                                     unsigned long long b,
                                                     unsigned long long c) {
    unsigned long long d;
    asm("fma.rn.f32x2 %0, %1, %2, %3;" : "=l"(d) : "l"(a), "l"(b), "l"(c));
    return d;
}
__device__ __forceinline__ unsigned long long pack2(float lo, float hi) {
    unsigned long long d;
    asm("mov.b64 %0, {%1, %2};" : "=l"(d) : "f"(lo), "f"(hi));
    return d;
}
__device__ __forceinline__ void unpack2(unsigned long long v, float& lo, float& hi) {
    asm("mov.b64 {%0, %1}, %2;" : "=f"(lo), "=f"(hi) : "l"(v));
}

// ================= init: twiddle tables =================
__global__ void init_tables_kernel() {
    int t = blockIdx.x * blockDim.x + threadIdx.x;
    int stride = gridDim.x * blockDim.x;
    for (int i = t; i < 64 * 64; i += stride) {
        int j = i >> 6, a = i & 63;
        float s, c;
        sincospif((float)(j * a) * (1.0f / 32.0f), &s, &c);   // 2*pi*j*a/64
        g_dft64[i] = make_float2(c, s);
    }
    for (int i = t; i < NH * NTAU; i += stride) {
        int h = i / NTAU, tau = i - h * NTAU;
        float s, c;
        sincospif((float)(h * tau) * (1.0f / 2048.0f), &s, &c); // 2*pi*h*tau/4096
        float w = ((h == 0) ? 1.0f : 2.0f) * (1.0f / (float)KLEN);
        g_lag4[i] = make_float4(w * c, w * c, w * s, w * s);
    }
}

// ================= FFT (64x64 four-step, double-folded stage 1) + PHAT =================
// x[k], k = 64*a + b.
// Stage 1 (real input, a-folding): for a=1..31: xe=x_a+x_{64-a}, xo=x_a-x_{64-a}
//   yr(d) = x0 + (-1)^d x32 + sum_a xe cos(2pi a d/64);  yi(d) = -sum_a xo sin(2pi a d/64)
//   only d<=32 computed; Z[64-d] from Hermitian symmetry via twiddle rotation.
// Stage 2: X[64c+d] = sum_b Z[d][b] * W64^{bc}, f <= 2048 only. Then PHAT normalize.
__global__ __launch_bounds__(256) void fft_phat_kernel(const float* __restrict__ x) {
    extern __shared__ float smem[];
    float2* xf  = (float2*)smem;            // [33][64]: a*64+b -> (xe,xo); a=0 -> (x0,x32)
    float2* Yt  = xf + 33 * 64;             // [b][d]: b*66 + d (padded)
    float2* dft = Yt + 64 * 66;             // rows j=0..32 of the 64-pt DFT table

    const int t = threadIdx.x;
    const float* xin = x + (size_t)blockIdx.x * KLEN;

    for (int i = t; i < 33 * 64; i += 256) dft[i] = g_dft64[i];
    for (int i = t; i < 32 * 64; i += 256) {
        int a = i >> 6, b = i & 63;
        if (a == 0) {
            xf[b] = make_float2(xin[b], xin[32 * 64 + b]);
        } else {
            float v1 = xin[a * 64 + b];
            float v2 = xin[(64 - a) * 64 + b];
            xf[a * 64 + b] = make_float2(v1 + v2, v1 - v2);
        }
    }
    __syncthreads();

    // ---- stage 1 (d <= 32) + twiddle + Hermitian mirror ----
    {
        int b = t & 63, d0 = t >> 6;
        float2 e = dft[64 + b];      // (cos, sin)(2*pi*b/64)
        float2 x03 = xf[b];          // (x0, x32)
        #pragma unroll
        for (int i = 0; i < 9; i++) {
            int d = d0 + 4 * i;
            if (d <= 32) {
                const float2* row = dft + d * 64;
                float yr = x03.x + ((d & 1) ? -x03.y : x03.y);
                float yi = 0.f;
                #pragma unroll 8
                for (int a = 1; a < 32; a++) {
                    float2 v = xf[a * 64 + b];
                    float2 cs = row[a];
                    yr += v.x * cs.x;
                    yi -= v.y * cs.y;
                }
                float s, c;
                sincospif((float)(b * d) * (1.0f / 2048.0f), &s, &c); // W4096^{bd} = c - i s
                Yt[b * 66 + d] = make_float2(yr * c + yi * s, yi * c - yr * s);
                if (d >= 1 && d <= 31) {
                    float tmr = e.x * c + e.y * s;     // cos(2pi b/64 - th)
                    float tms = e.y * c - e.x * s;     // sin(2pi b/64 - th)
                    Yt[b * 66 + (64 - d)] =
                        make_float2(yr * tmr - yi * tms, -(yr * tms + yi * tmr));
                }
            }
        }
    }
    __syncthreads();

    // ---- stage 2: f = 64c + d, f <= 2048 (c in [0,32]) ----
    {
        int d = t & 63, c0 = t >> 6;
        float2* outp = g_spec + (size_t)blockIdx.x * NFREQ;
        #pragma unroll
        for (int j = 0; j < 9; j++) {
            int cc = c0 + 4 * j;
            if (cc <= 32) {
                float Xr = 0.f, Xi = 0.f;
                const float2* row = dft + cc * 64;
                #pragma unroll 8
                for (int bb = 0; bb < 64; bb++) {
                    float2 z = Yt[bb * 66 + d];
                    float2 cs = row[bb];
                    Xr += z.x * cs.x + z.y * cs.y;
                    Xi += z.y * cs.x - z.x * cs.y;
                }
                int f = cc * 64 + d;
                if (f <= 2048) {
                    float mag = sqrtf(Xr * Xr + Xi * Xi);
                    float inv = 1.0f / (mag + 1e-12f);
                    outp[f] = make_float2(Xr * inv, Xi * inv);
                }
            }
        }
    }
}

// ================= GCC: folded cross-spectrum x lag twiddles (f32x2 packed) =================
// grid (16 batch-groups, 8 slices), block 320 = 4 x 80 threads.
// Each 80-thread group handles ONE batch: thread = one pair, ALL 26 taus, full 129-freq
// slice. Accumulators live in registers; no intra-CTA reduction, no atomics.
//   even tau: g+ = wc*(U1+U2) - ws*(V1-V2);  g- = wc*(U1+U2) + ws*(V1-V2)
//   odd  tau: g+ = wc*(U1-U2) - ws*(V1+V2);  g- = wc*(U1-U2) + ws*(V1+V2)
__global__ __launch_bounds__(GCC_BLOCK) void gcc_kernel() {
    extern __shared__ float smem[];
    float2* suA = (float2*)smem;                 // [BPG][12][CH] spectra at f
    float2* suB = suA + BPG * NSIG * CH;         // [BPG][12][CH] spectra at 2048-f
    float4* T   = (float4*)(suB + BPG * NSIG * CH);  // [CH][26] packed twiddles

    const int t = threadIdx.x;
    const int bg = blockIdx.x;                   // batch group (4 batches)
    const int f0 = blockIdx.y * CH;

    for (int i = t; i < BPG * NSIG * CH; i += GCC_BLOCK) {
        int g = i / (NSIG * CH);
        int r = i - g * (NSIG * CH);
        int sig = r / CH, hl = r - sig * CH;
        int f = f0 + hl;
        const float2* sp = g_spec + ((size_t)(bg * BPG + g) * NSIG + sig) * NFREQ;
        suA[i] = (f <= 1024) ? sp[f] : make_float2(0.f, 0.f);
        suB[i] = (f <= 1023) ? sp[2048 - f] : make_float2(0.f, 0.f);
    }
    for (int i = t; i < CH * NTAU; i += GCC_BLOCK) {
        int hl = i / NTAU;
        int f = f0 + hl;
        T[i] = (f <= 1024) ? g_lag4[f * NTAU + (i - hl * NTAU)]
                           : make_float4(0.f, 0.f, 0.f, 0.f);
    }
    __syncthreads();

    const int g = t / 80, u = t - g * 80;
    if (u >= NPAIR) return;

    // decode triangular pair u -> (n, m), n <= m
    int n = 0, rem = u;
    #pragma unroll
    for (int k = 0; k < NSIG; k++) {
        int cnt = NSIG - k;
        if (rem < cnt) { n = k; break; }
        rem -= cnt;
    }
    const int m = n + rem;

    const float2* bA = suA + g * (NSIG * CH);
    const float2* bB = suB + g * (NSIG * CH);
    const float2* pAn = bA + n * CH;
    const float2* pAm = bA + m * CH;
    const float2* pBn = bB + n * CH;
    const float2* pBm = bB + m * CH;

    unsigned long long acc[NTAU];   // packed (g+, g-)
    #pragma unroll
    for (int i = 0; i < NTAU; i++) acc[i] = 0ull;

    for (int hl = 0; hl < CH; hl++) {
        float2 a1 = pAn[hl], b1 = pAm[hl];
        float2 a2 = pBn[hl], b2 = pBm[hl];
        float U1 = a1.x * b1.x + a1.y * b1.y;
        float V1 = a1.y * b1.x - a1.x * b1.y;
        float U2 = a2.x * b2.x + a2.y * b2.y;
        float V2 = a2.y * b2.x - a2.x * b2.y;
        float Ue = U1 + U2, Uo = U1 - U2;
        float Vme = V1 - V2, Vpo = V1 + V2;
        unsigned long long pUe = pack2(Ue, Ue);
        unsigned long long pUo = pack2(Uo, Uo);
        unsigned long long pVe = pack2(-Vme, Vme);
        unsigned long long pVo = pack2(-Vpo, Vpo);
        const longlong2* tw = (const longlong2*)(T + (size_t)hl * NTAU);
        #pragma unroll
        for (int tau = 0; tau < NTAU; tau++) {
            longlong2 w = tw[tau];   // .x = (wc,wc), .y = (ws,ws)
            acc[tau] = fma_x2((unsigned long long)w.x, (tau & 1) ? pUo : pUe, acc[tau]);
            acc[tau] = fma_x2((unsigned long long)w.y, (tau & 1) ? pVo : pVe, acc[tau]);
        }
    }

    unsigned long long* pr = &g_part2[blockIdx.y][bg * BPG + g][u][0];
    #pragma unroll
    for (int tau = 0; tau < NTAU; tau++) pr[tau] = acc[tau];
}

// ================= reduce partials + triangular mirror expansion =================
// thread = (batch, pair, tau); sums 8 slices, writes up to 4 output elements.
__global__ void reduce_kernel(float* __restrict__ out) {
    int i = blockIdx.x * blockDim.x + threadIdx.x;
    if (i >= NBATCH * NPAIR * NTAU) return;
    int b = i / (NPAIR * NTAU);
    int r = i - b * (NPAIR * NTAU);
    int p = r / NTAU, tau = r - p * NTAU;

    float gp = 0.f, gm = 0.f;
    #pragma unroll
    for (int s = 0; s < NS; s++) {
        float lo, hi;
        unpack2(g_part2[s][b][p][tau], lo, hi);
        gp += lo; gm += hi;
    }

    int n = 0, rem = p;
    #pragma unroll
    for (int k = 0; k < NSIG; k++) {
        int cnt = NSIG - k;
        if (rem < cnt) { n = k; break; }
        rem -= cnt;
    }
    int m = n + rem;

    float* ob = out + (size_t)b * OUTB;
    ob[(n * NSIG + m) * NLAG + tau] = gp;                     // g_nm[+tau]
    if (tau > 0) ob[(n * NSIG + m) * NLAG + NLAG - tau] = gm; // g_nm[-tau]
    if (n != m) {
        ob[(m * NSIG + n) * NLAG + tau] = gm;                 // g_mn[+tau] = g_nm[-tau]
        if (tau > 0) ob[(m * NSIG + n) * NLAG + NLAG - tau] = gp;
    }
}

// ================= launch =================
extern "C" void kernel_launch(void* const* d_in, const int* in_sizes, int n_in,
                              void* d_out, int out_size) {
    const float* x = (const float*)d_in[0];
    float* out = (float*)d_out;

    const int fft_smem = (33 * 64 + 64 * 66 + 33 * 64) * (int)sizeof(float2);   // 67,584
    const int gcc_smem = 2 * BPG * NSIG * CH * (int)sizeof(float2)
                       + CH * NTAU * (int)sizeof(float4);                        // 152,736

    cudaFuncSetAttribute(fft_phat_kernel, cudaFuncAttributeMaxDynamicSharedMemorySize, fft_smem);
    cudaFuncSetAttribute(gcc_kernel,      cudaFuncAttributeMaxDynamicSharedMemorySize, gcc_smem);

    init_tables_kernel<<<128, 256>>>();
    fft_phat_kernel<<<NBATCH * NSIG, 256, fft_smem>>>(x);
    gcc_kernel<<<dim3(NBATCH / BPG, NS), GCC_BLOCK, gcc_smem>>>();
    const int rthreads = NBATCH * NPAIR * NTAU;
    reduce_kernel<<<(rthreads + 255) / 256, 256>>>(out);
}

// round 4
// speedup vs baseline: 2.8955x; 1.4184x over previous
#include <cuda_runtime.h>
#include <math.h>

#define KLEN   4096
#define NFREQ  2049      // K/2 + 1
#define NH     1025      // folded frequencies h = 0..1024 (f=h paired with f=2048-h)
#define NSIG   12
#define NBATCH 64
#define NLAG   51        // 2*25 + 1
#define NTAU   26        // tau = 0..25
#define NPAIR  78        // 12*13/2 unique (n<=m) pairs
#define NS     9         // frequency slices (144 CTAs = one full wave on 148 SMs)
#define CH     114       // folded freqs per slice (9*114 = 1026 >= 1025)
#define BPG    4         // batches per gcc CTA
#define GCC_BLOCK 320    // 4 batch-groups x 80 threads (78 active pairs each)
#define OUTB   (NSIG*NSIG*NLAG)   // 7344 floats per batch

// -------- device scratch (static: no allocations allowed) --------
__device__ float2 g_dft64[64 * 64];               // (cos,sin) of 2*pi*j*a/64 at [j*64+a]
__device__ float4 g_lag4[NH * NTAU];              // (w*c, w*c, w*s, w*s) at [h*26+tau]
__device__ float2 g_spec[NBATCH * NSIG * NFREQ];  // PHAT-normalized spectra
__device__ unsigned long long g_part2[NS][NBATCH][NPAIR][NTAU];  // packed (g+, g-)

// -------- packed fp32x2 helpers --------
__device__ __forceinline__ unsigned long long fma_x2(unsigned long long a,
                                                     unsigned long long b,
                                                     unsigned long long c) {
    unsigned long long d;
    asm("fma.rn.f32x2 %0, %1, %2, %3;" : "=l"(d) : "l"(a), "l"(b), "l"(c));
    return d;
}
__device__ __forceinline__ unsigned long long pack2(float lo, float hi) {
    unsigned long long d;
    asm("mov.b64 %0, {%1, %2};" : "=l"(d) : "f"(lo), "f"(hi));
    return d;
}
__device__ __forceinline__ void unpack2(unsigned long long v, float& lo, float& hi) {
    asm("mov.b64 {%0, %1}, %2;" : "=f"(lo), "=f"(hi) : "l"(v));
}

// ================= init: twiddle tables =================
__global__ void init_tables_kernel() {
    int t = blockIdx.x * blockDim.x + threadIdx.x;
    int stride = gridDim.x * blockDim.x;
    for (int i = t; i < 64 * 64; i += stride) {
        int j = i >> 6, a = i & 63;
        float s, c;
        sincospif((float)(j * a) * (1.0f / 32.0f), &s, &c);   // 2*pi*j*a/64
        g_dft64[i] = make_float2(c, s);
    }
    for (int i = t; i < NH * NTAU; i += stride) {
        int h = i / NTAU, tau = i - h * NTAU;
        float s, c;
        sincospif((float)(h * tau) * (1.0f / 2048.0f), &s, &c); // 2*pi*h*tau/4096
        float w = ((h == 0) ? 1.0f : 2.0f) * (1.0f / (float)KLEN);
        g_lag4[i] = make_float4(w * c, w * c, w * s, w * s);
    }
}

// ================= FFT (64x64 four-step, fully folded, register-blocked) + PHAT ======
// x[k], k = 64*a + b.
// Stage 1 (a-folding, real input): xe=x_a+x_{64-a}, xo=x_a-x_{64-a}:
//   Y(d) = (yr, yi): yr = x0 + (-1)^d x32 + sum_a xe cos;  yi = -sum_a xo sin
//   packed: acc += (xe, -xo) * (cos, sin). Only d<=32; Z[64-d] via Hermitian mirror.
// Stage 2 (b-folding): ze=Z_b+Z_{64-b}, zo=Z_b-Z_{64-b}:
//   X[64c+d] = Z0 + (-1)^c Z32 + sum_{b=1..31} [ze*cos(2pi bc/64) - i*zo*sin(...)]
// Loops are a/b-outer, output-index-inner with 9 register accumulators per thread.
__global__ __launch_bounds__(256) void fft_phat_kernel(const float* __restrict__ x) {
    extern __shared__ float smem[];
    float2* xf  = (float2*)smem;            // [32][64]: a*64+b -> (xe,xo); a=0 -> (x0,x32)
    float2* Yt  = xf + 32 * 64;             // [b][d]: b*66 + d (padded)
    float2* dft = Yt + 64 * 66;             // rows j=0..32 valid; padded to 36 rows

    const int t = threadIdx.x;
    const float* xin = x + (size_t)blockIdx.x * KLEN;

    for (int i = t; i < 33 * 64; i += 256) dft[i] = g_dft64[i];
    for (int i = t; i < 32 * 64; i += 256) {
        int a = i >> 6, b = i & 63;
        if (a == 0) {
            xf[b] = make_float2(xin[b], xin[32 * 64 + b]);
        } else {
            float v1 = xin[a * 64 + b];
            float v2 = xin[(64 - a) * 64 + b];
            xf[a * 64 + b] = make_float2(v1 + v2, v1 - v2);
        }
    }
    __syncthreads();

    const int bb = t & 63, q0 = t >> 6;

    // ---- stage 1: 9 packed accumulators (yr, yi) for d = q0 + 4i ----
    {
        unsigned long long acc[9];
        #pragma unroll
        for (int i = 0; i < 9; i++) acc[i] = 0ull;

        for (int a = 1; a < 32; a++) {
            float2 v = xf[a * 64 + bb];
            unsigned long long vp = pack2(v.x, -v.y);
            const float2* col = dft + a;
            #pragma unroll
            for (int i = 0; i < 9; i++) {
                int d = q0 + 4 * i;                    // d<=35; rows padded, junk discarded
                unsigned long long cs = *(const unsigned long long*)(col + d * 64);
                acc[i] = fma_x2(vp, cs, acc[i]);
            }
        }

        float2 e = dft[64 + bb];       // (cos, sin)(2*pi*b/64)
        float2 x03 = xf[bb];           // (x0, x32)
        #pragma unroll
        for (int i = 0; i < 9; i++) {
            int d = q0 + 4 * i;
            if (d <= 32) {
                float yr, yi;
                unpack2(acc[i], yr, yi);
                yr += x03.x + ((d & 1) ? -x03.y : x03.y);
                float s, c;
                sincospif((float)(bb * d) * (1.0f / 2048.0f), &s, &c); // W4096^{bd}=c-is
                Yt[bb * 66 + d] = make_float2(yr * c + yi * s, yi * c - yr * s);
                if (d >= 1 && d <= 31) {
                    float tmr = e.x * c + e.y * s;     // cos(2pi b/64 - th)
                    float tms = e.y * c - e.x * s;     // sin(2pi b/64 - th)
                    Yt[bb * 66 + (64 - d)] =
                        make_float2(yr * tmr - yi * tms, -(yr * tms + yi * tmr));
                }
            }
        }
    }
    __syncthreads();

    // ---- stage 2: d = bb, cc = q0 + 4j; b-folded, 9 complex accumulators ----
    {
        const int d = bb;
        float Xr[9], Xi[9];
        float2 z0  = Yt[0 * 66 + d];
        float2 z32 = Yt[32 * 66 + d];
        #pragma unroll
        for (int j = 0; j < 9; j++) {
            int cc = q0 + 4 * j;
            float sg = (cc & 1) ? -1.f : 1.f;
            Xr[j] = z0.x + sg * z32.x;
            Xi[j] = z0.y + sg * z32.y;
        }

        for (int b = 1; b < 32; b++) {
            float2 z1 = Yt[b * 66 + d];
            float2 z2 = Yt[(64 - b) * 66 + d];
            float zex = z1.x + z2.x, zey = z1.y + z2.y;
            float zox = z1.x - z2.x, zoy = z1.y - z2.y;
            const float2* col = dft + b;
            #pragma unroll
            for (int j = 0; j < 9; j++) {
                int cc = q0 + 4 * j;                   // <=35; padded rows, junk discarded
                float2 cs = col[cc * 64];
                Xr[j] += zex * cs.x + zoy * cs.y;
                Xi[j] += zey * cs.x - zox * cs.y;
            }
        }

        float2* outp = g_spec + (size_t)blockIdx.x * NFREQ;
        #pragma unroll
        for (int j = 0; j < 9; j++) {
            int cc = q0 + 4 * j;
            int f = cc * 64 + d;
            if (cc <= 32 && f <= 2048) {
                float mag = sqrtf(Xr[j] * Xr[j] + Xi[j] * Xi[j]);
                float inv = 1.0f / (mag + 1e-12f);
                outp[f] = make_float2(Xr[j] * inv, Xi[j] * inv);
            }
        }
    }
}

// ================= GCC: folded cross-spectrum x lag twiddles (f32x2 packed) ==========
// grid (16 batch-groups, 9 slices), block 320 = 4 x 80 threads.
// Each 80-thread group handles ONE batch: thread = one pair, ALL 26 taus, 114-freq
// slice. Register accumulators; no reductions, no atomics.
__global__ __launch_bounds__(GCC_BLOCK) void gcc_kernel() {
    extern __shared__ float smem[];
    float2* suA = (float2*)smem;                     // [BPG][12][CH] spectra at f
    float2* suB = suA + BPG * NSIG * CH;             // [BPG][12][CH] spectra at 2048-f
    float4* T   = (float4*)(suB + BPG * NSIG * CH);  // [CH][26] packed twiddles

    const int t = threadIdx.x;
    const int bg = blockIdx.x;
    const int f0 = blockIdx.y * CH;

    for (int i = t; i < BPG * NSIG * CH; i += GCC_BLOCK) {
        int g = i / (NSIG * CH);
        int r = i - g * (NSIG * CH);
        int sig = r / CH, hl = r - sig * CH;
        int f = f0 + hl;
        const float2* sp = g_spec + ((size_t)(bg * BPG + g) * NSIG + sig) * NFREQ;
        suA[i] = (f <= 1024) ? sp[f] : make_float2(0.f, 0.f);
        suB[i] = (f <= 1023) ? sp[2048 - f] : make_float2(0.f, 0.f);
    }
    for (int i = t; i < CH * NTAU; i += GCC_BLOCK) {
        int hl = i / NTAU;
        int f = f0 + hl;
        T[i] = (f <= 1024) ? g_lag4[f * NTAU + (i - hl * NTAU)]
                           : make_float4(0.f, 0.f, 0.f, 0.f);
    }
    __syncthreads();

    const int g = t / 80, u = t - g * 80;
    if (u >= NPAIR) return;

    int n = 0, rem = u;
    #pragma unroll
    for (int k = 0; k < NSIG; k++) {
        int cnt = NSIG - k;
        if (rem < cnt) { n = k; break; }
        rem -= cnt;
    }
    const int m = n + rem;

    const float2* bA = suA + g * (NSIG * CH);
    const float2* bB = suB + g * (NSIG * CH);
    const float2* pAn = bA + n * CH;
    const float2* pAm = bA + m * CH;
    const float2* pBn = bB + n * CH;
    const float2* pBm = bB + m * CH;

    unsigned long long acc[NTAU];   // packed (g+, g-)
    #pragma unroll
    for (int i = 0; i < NTAU; i++) acc[i] = 0ull;

    for (int hl = 0; hl < CH; hl++) {
        float2 a1 = pAn[hl], b1 = pAm[hl];
        float2 a2 = pBn[hl], b2 = pBm[hl];
        float U1 = a1.x * b1.x + a1.y * b1.y;
        float V1 = a1.y * b1.x - a1.x * b1.y;
        float U2 = a2.x * b2.x + a2.y * b2.y;
        float V2 = a2.y * b2.x - a2.x * b2.y;
        float Ue = U1 + U2, Uo = U1 - U2;
        float Vme = V1 - V2, Vpo = V1 + V2;
        unsigned long long pUe = pack2(Ue, Ue);
        unsigned long long pUo = pack2(Uo, Uo);
        unsigned long long pVe = pack2(-Vme, Vme);
        unsigned long long pVo = pack2(-Vpo, Vpo);
        const longlong2* tw = (const longlong2*)(T + (size_t)hl * NTAU);
        #pragma unroll
        for (int tau = 0; tau < NTAU; tau++) {
            longlong2 w = tw[tau];   // .x = (wc,wc), .y = (ws,ws)
            acc[tau] = fma_x2((unsigned long long)w.x, (tau & 1) ? pUo : pUe, acc[tau]);
            acc[tau] = fma_x2((unsigned long long)w.y, (tau & 1) ? pVo : pVe, acc[tau]);
        }
    }

    unsigned long long* pr = &g_part2[blockIdx.y][bg * BPG + g][u][0];
    #pragma unroll
    for (int tau = 0; tau < NTAU; tau++) pr[tau] = acc[tau];
}

// ================= reduce partials + triangular mirror expansion =================
__global__ void reduce_kernel(float* __restrict__ out) {
    int i = blockIdx.x * blockDim.x + threadIdx.x;
    if (i >= NBATCH * NPAIR * NTAU) return;
    int b = i / (NPAIR * NTAU);
    int r = i - b * (NPAIR * NTAU);
    int p = r / NTAU, tau = r - p * NTAU;

    float gp = 0.f, gm = 0.f;
    #pragma unroll
    for (int s = 0; s < NS; s++) {
        float lo, hi;
        unpack2(g_part2[s][b][p][tau], lo, hi);
        gp += lo; gm += hi;
    }

    int n = 0, rem = p;
    #pragma unroll
    for (int k = 0; k < NSIG; k++) {
        int cnt = NSIG - k;
        if (rem < cnt) { n = k; break; }
        rem -= cnt;
    }
    int m = n + rem;

    float* ob = out + (size_t)b * OUTB;
    ob[(n * NSIG + m) * NLAG + tau] = gp;
    if (tau > 0) ob[(n * NSIG + m) * NLAG + NLAG - tau] = gm;
    if (n != m) {
        ob[(m * NSIG + n) * NLAG + tau] = gm;
        if (tau > 0) ob[(m * NSIG + n) * NLAG + NLAG - tau] = gp;
    }
}

// ================= launch =================
extern "C" void kernel_launch(void* const* d_in, const int* in_sizes, int n_in,
                              void* d_out, int out_size) {
    const float* x = (const float*)d_in[0];
    float* out = (float*)d_out;

    const int fft_smem = (32 * 64 + 64 * 66 + 36 * 64) * (int)sizeof(float2);   // 68,608
    const int gcc_smem = 2 * BPG * NSIG * CH * (int)sizeof(float2)
                       + CH * NTAU * (int)sizeof(float4);                        // 134,976

    cudaFuncSetAttribute(fft_phat_kernel, cudaFuncAttributeMaxDynamicSharedMemorySize, fft_smem);
    cudaFuncSetAttribute(gcc_kernel,      cudaFuncAttributeMaxDynamicSharedMemorySize, gcc_smem);

    init_tables_kernel<<<128, 256>>>();
    fft_phat_kernel<<<NBATCH * NSIG, 256, fft_smem>>>(x);
    gcc_kernel<<<dim3(NBATCH / BPG, NS), GCC_BLOCK, gcc_smem>>>();
    const int rthreads = NBATCH * NPAIR * NTAU;
    reduce_kernel<<<(rthreads + 255) / 256, 256>>>(out);
}